// round 2
// baseline (speedup 1.0000x reference)
#include <cuda_runtime.h>
#include <cuda_bf16.h>
#include <cstdint>

// Problem constants
constexpr int B = 2, H = 16, S = 2048, D = 64;
constexpr int BH = B * H;                      // 32
constexpr float SCALE = 0.125f;                // 1/sqrt(64)
constexpr int TQ = 128, TK = 128;              // tile sizes
constexpr size_t CTX_ELEMS = (size_t)BH * S * D;          // 4,194,304

// Per-row softmax stats scratch (tiny, allowed as __device__ globals)
__device__ float g_m[BH * S];
__device__ float g_l[BH * S];

// ---------------------------------------------------------------------------
// Pass 1: S = (Q K^T) * scale with causal mask; write raw scores into the
// prob region of d_out (scratch); compute per-row online max m and sum l.
// Grid: (S/TQ, BH). 256 threads. Each thread owns an 8x8 score sub-tile with
// strided mapping: row = ty + 16*rr, col = tx + 16*cc.
// ---------------------------------------------------------------------------
__global__ void __launch_bounds__(256)
attn_pass1(const float* __restrict__ Q, const float* __restrict__ K,
           float* __restrict__ SC)
{
    extern __shared__ float sm[];
    float* sQ = sm;               // 128 rows x 68 floats (padded)
    float* sK = sm + 128 * 68;    // 128 rows x 68 floats

    const int tid = threadIdx.x;
    const int tx = tid & 15;
    const int ty = tid >> 4;
    const int qt = blockIdx.x;
    const int bh = blockIdx.y;
    const int r0 = qt * TQ;

    // Load Q tile (coalesced float4), padded row stride 68 floats (16B aligned)
    {
        const float* qbase = Q + ((size_t)bh * S + r0) * D;
        for (int i = tid; i < 128 * 16; i += 256) {
            int row = i >> 4, c4 = i & 15;
            float4 v = ((const float4*)(qbase + row * D))[c4];
            *((float4*)(sQ + row * 68 + c4 * 4)) = v;
        }
    }

    float m[8], l[8];
#pragma unroll
    for (int rr = 0; rr < 8; rr++) { m[rr] = -1e30f; l[rr] = 0.0f; }

    for (int kt = 0; kt <= qt; ++kt) {
        __syncthreads();   // previous tile's compute done before overwriting sK
        {
            const float* kbase = K + ((size_t)bh * S + kt * TK) * D;
            for (int i = tid; i < 128 * 16; i += 256) {
                int row = i >> 4, c4 = i & 15;
                float4 v = ((const float4*)(kbase + row * D))[c4];
                *((float4*)(sK + row * 68 + c4 * 4)) = v;
            }
        }
        __syncthreads();   // sQ (first iter) + sK visible

        float acc[8][8];
#pragma unroll
        for (int rr = 0; rr < 8; rr++)
#pragma unroll
            for (int cc = 0; cc < 8; cc++) acc[rr][cc] = 0.0f;

#pragma unroll 1
        for (int kk4 = 0; kk4 < 16; ++kk4) {
            float4 qf[8], kf[8];
#pragma unroll
            for (int rr = 0; rr < 8; rr++)
                qf[rr] = *((const float4*)(sQ + (ty + 16 * rr) * 68 + kk4 * 4));
#pragma unroll
            for (int cc = 0; cc < 8; cc++)
                kf[cc] = *((const float4*)(sK + (tx + 16 * cc) * 68 + kk4 * 4));
#pragma unroll
            for (int rr = 0; rr < 8; rr++)
#pragma unroll
                for (int cc = 0; cc < 8; cc++) {
                    acc[rr][cc] += qf[rr].x * kf[cc].x;
                    acc[rr][cc] += qf[rr].y * kf[cc].y;
                    acc[rr][cc] += qf[rr].z * kf[cc].z;
                    acc[rr][cc] += qf[rr].w * kf[cc].w;
                }
        }

        const bool diag = (kt == qt);
#pragma unroll
        for (int rr = 0; rr < 8; rr++) {
            const int row = ty + 16 * rr;
            float sv[8];
            float tmax = -1e30f;
#pragma unroll
            for (int cc = 0; cc < 8; cc++) {
                const int col = tx + 16 * cc;
                float s = acc[rr][cc] * SCALE;
                if (diag && col > row) s = -1e9f;   // causal mask fill
                sv[cc] = s;
                tmax = fmaxf(tmax, s);
            }
            // row max across the 16 tx lanes
            tmax = fmaxf(tmax, __shfl_xor_sync(0xffffffffu, tmax, 1));
            tmax = fmaxf(tmax, __shfl_xor_sync(0xffffffffu, tmax, 2));
            tmax = fmaxf(tmax, __shfl_xor_sync(0xffffffffu, tmax, 4));
            tmax = fmaxf(tmax, __shfl_xor_sync(0xffffffffu, tmax, 8));

            const float mn = fmaxf(m[rr], tmax);
            float psum = 0.0f;
#pragma unroll
            for (int cc = 0; cc < 8; cc++) psum += __expf(sv[cc] - mn);
            psum += __shfl_xor_sync(0xffffffffu, psum, 1);
            psum += __shfl_xor_sync(0xffffffffu, psum, 2);
            psum += __shfl_xor_sync(0xffffffffu, psum, 4);
            psum += __shfl_xor_sync(0xffffffffu, psum, 8);

            l[rr] = l[rr] * __expf(m[rr] - mn) + psum;
            m[rr] = mn;

            // store raw (masked) scores: 16 consecutive lanes -> 64B segments
            float* dst = SC + ((size_t)bh * S + r0 + row) * S + kt * TK;
#pragma unroll
            for (int cc = 0; cc < 8; cc++) dst[tx + 16 * cc] = sv[cc];
        }
    }

    if (tx == 0) {
#pragma unroll
        for (int rr = 0; rr < 8; rr++) {
            const int gi = bh * S + r0 + ty + 16 * rr;
            g_m[gi] = m[rr];
            g_l[gi] = l[rr];
        }
    }
}

// ---------------------------------------------------------------------------
// Pass 2: read scores, probs = exp(s-m)/l -> write probs (gmem + smem),
// accumulate context = P @ V, zero-fill non-causal columns, write context.
// ---------------------------------------------------------------------------
__global__ void __launch_bounds__(256)
attn_pass2(const float* __restrict__ V, float* __restrict__ SC,
           float* __restrict__ CTX)
{
    extern __shared__ float sm[];
    float* sVt = sm;                 // 64 d-rows x 132 cols (transposed V)
    float* sP  = sm + 64 * 132;      // 128 rows x 132 cols

    const int tid = threadIdx.x;
    const int tx = tid & 15;         // prob mapping: col group
    const int ty = tid >> 4;         // prob mapping: row group
    const int dgrp = tid & 15;       // PV mapping: d group (d = dgrp*4 + dd)
    const int rowgrp = tid >> 4;     // PV mapping: row = rowgrp + 16*rr
    const int qt = blockIdx.x;
    const int bh = blockIdx.y;
    const int r0 = qt * TQ;

    float m[8], rl[8];
#pragma unroll
    for (int rr = 0; rr < 8; rr++) {
        const int gi = bh * S + r0 + ty + 16 * rr;
        m[rr] = g_m[gi];
        rl[rr] = 1.0f / g_l[gi];
    }

    float ctx[8][4];
#pragma unroll
    for (int rr = 0; rr < 8; rr++)
#pragma unroll
        for (int dd = 0; dd < 4; dd++) ctx[rr][dd] = 0.0f;

    for (int kt = 0; kt <= qt; ++kt) {
        __syncthreads();   // previous PV done before overwriting sVt / sP

        // Load V tile transposed: sVt[d][col]
        {
            const float* vbase = V + ((size_t)bh * S + kt * TK) * D;
            for (int i = tid; i < 128 * 16; i += 256) {
                int col = i >> 4, d4 = i & 15;
                float4 v = ((const float4*)(vbase + col * D))[d4];
                sVt[(d4 * 4 + 0) * 132 + col] = v.x;
                sVt[(d4 * 4 + 1) * 132 + col] = v.y;
                sVt[(d4 * 4 + 2) * 132 + col] = v.z;
                sVt[(d4 * 4 + 3) * 132 + col] = v.w;
            }
        }

        // probs: read scores, exponentiate, write to gmem + smem
#pragma unroll
        for (int rr = 0; rr < 8; rr++) {
            const int row = ty + 16 * rr;
            float* srow = SC + ((size_t)bh * S + r0 + row) * S + kt * TK;
#pragma unroll
            for (int cc = 0; cc < 8; cc++) {
                const int col = tx + 16 * cc;
                const float p = __expf(srow[col] - m[rr]) * rl[rr];
                srow[col] = p;
                sP[row * 132 + col] = p;
            }
        }
        __syncthreads();

        // PV: ctx[row][d] += sum_col sP[row][col] * sVt[d][col]
#pragma unroll 2
        for (int c4 = 0; c4 < 32; ++c4) {
            float4 pv[8];
#pragma unroll
            for (int rr = 0; rr < 8; rr++)
                pv[rr] = *((const float4*)(sP + (rowgrp + 16 * rr) * 132 + c4 * 4));
            float4 vv[4];
#pragma unroll
            for (int dd = 0; dd < 4; dd++)
                vv[dd] = *((const float4*)(sVt + (dgrp * 4 + dd) * 132 + c4 * 4));
#pragma unroll
            for (int rr = 0; rr < 8; rr++)
#pragma unroll
                for (int dd = 0; dd < 4; dd++) {
                    ctx[rr][dd] += pv[rr].x * vv[dd].x;
                    ctx[rr][dd] += pv[rr].y * vv[dd].y;
                    ctx[rr][dd] += pv[rr].z * vv[dd].z;
                    ctx[rr][dd] += pv[rr].w * vv[dd].w;
                }
        }
    }

    // Zero-fill the non-causal (upper) columns of this q-tile's prob rows
    {
        const int c0 = (qt + 1) * TK;
        if (c0 < S) {
            const int width4 = (S - c0) >> 2;
            const float4 z = make_float4(0.f, 0.f, 0.f, 0.f);
            for (int i = tid; i < 128 * width4; i += 256) {
                const int row = i / width4;
                const int c4 = i - row * width4;
                *((float4*)(SC + ((size_t)bh * S + r0 + row) * S + c0 + 4 * c4)) = z;
            }
        }
    }

    // Write context (coalesced float4)
#pragma unroll
    for (int rr = 0; rr < 8; rr++) {
        const int row = rowgrp + 16 * rr;
        float4 o = make_float4(ctx[rr][0], ctx[rr][1], ctx[rr][2], ctx[rr][3]);
        ((float4*)(CTX + ((size_t)bh * S + r0 + row) * D))[dgrp] = o;
    }
}

// ---------------------------------------------------------------------------
extern "C" void kernel_launch(void* const* d_in, const int* in_sizes, int n_in,
                              void* d_out, int out_size)
{
    const float* q = (const float*)d_in[0];
    const float* k = (const float*)d_in[1];
    const float* v = (const float*)d_in[2];
    // d_in[3] = attn_mask (causal, known statically) — unused

    float* out = (float*)d_out;
    float* ctx = out;                 // [BH, S, D]
    float* sc  = out + CTX_ELEMS;     // [BH, S, S] — scratch scores, then probs

    const int smem1 = 2 * 128 * 68 * sizeof(float);             // 69,632 B
    const int smem2 = (64 * 132 + 128 * 132) * sizeof(float);   // 101,376 B
    cudaFuncSetAttribute(attn_pass1, cudaFuncAttributeMaxDynamicSharedMemorySize, smem1);
    cudaFuncSetAttribute(attn_pass2, cudaFuncAttributeMaxDynamicSharedMemorySize, smem2);

    dim3 grid(S / TQ, BH);   // (16, 32)
    attn_pass1<<<grid, 256, smem1>>>(q, k, sc);
    attn_pass2<<<grid, 256, smem2>>>(v, sc, ctx);
}

// round 5
// speedup vs baseline: 1.2459x; 1.2459x over previous
#include <cuda_runtime.h>
#include <cstdint>

// Problem constants
constexpr int S = 2048, D = 64;
constexpr int BH = 32;                      // B*H
constexpr float SCALE = 0.125f;             // 1/sqrt(64)
constexpr size_t CTX_ELEMS = (size_t)BH * S * D;

constexpr int PQ = 68;    // sQ row pitch (floats) — multiple of 4 for float4 stores
constexpr int PK = 134;   // sKt row pitch — even for 8B loads
constexpr int PV = 68;    // sV row pitch — multiple of 4 for float4 stores
constexpr int PP = 132;   // sP row pitch — multiple of 4

// Per-row softmax stats scratch
__device__ float g_m[BH * S];
__device__ float g_l[BH * S];

// ---- packed fp32x2 helpers (FFMA2: 2x fp32 FMA throughput on sm_103a) ----
__device__ __forceinline__ unsigned long long pack2(float lo, float hi) {
    unsigned long long r;
    asm("mov.b64 %0, {%1, %2};" : "=l"(r) : "r"(__float_as_uint(lo)), "r"(__float_as_uint(hi)));
    return r;
}
__device__ __forceinline__ unsigned long long dup2(float x) { return pack2(x, x); }
__device__ __forceinline__ float2 unpack2(unsigned long long v) {
    unsigned int a, b;
    asm("mov.b64 {%0, %1}, %2;" : "=r"(a), "=r"(b) : "l"(v));
    return make_float2(__uint_as_float(a), __uint_as_float(b));
}
__device__ __forceinline__ void fma2(unsigned long long& d, unsigned long long a, unsigned long long b) {
    asm("fma.rn.f32x2 %0, %1, %2, %3;" : "=l"(d) : "l"(a), "l"(b), "l"(d));
}

// ---------------------------------------------------------------------------
// Pass 1: raw masked scores -> SC (prob scratch region), online m/l -> g_m/g_l.
// Grid (8, 32): CTA pid handles q-tiles {pid, 15-pid} (17 k-tile units each).
// 256 threads; thread owns 8 rows x 8 cols; cols packed in f32x2 pairs.
// ---------------------------------------------------------------------------
__global__ void __launch_bounds__(256, 2)
attn_pass1(const float* __restrict__ Q, const float* __restrict__ K,
           float* __restrict__ SC)
{
    extern __shared__ float sm[];
    float* sQ  = sm;              // 128 x PQ  (row-major Q tile)
    float* sKt = sm + 128 * PQ;   // 64  x PK  (K transposed: [kk][col])

    const int tid = threadIdx.x;
    const int tx = tid & 15;
    const int ty = tid >> 4;
    const int pid = blockIdx.x;
    const int bh = blockIdx.y;

    for (int half = 0; half < 2; ++half) {
        const int qt = half ? (15 - pid) : pid;
        const int r0 = qt * 128;

        __syncthreads();  // protect sQ reuse across halves
        {
            const float* qbase = Q + ((size_t)bh * S + r0) * D;
            for (int i = tid; i < 128 * 16; i += 256) {
                int row = i >> 4, c4 = i & 15;
                float4 v = ((const float4*)(qbase + row * D))[c4];
                *((float4*)(sQ + row * PQ + c4 * 4)) = v;
            }
        }

        float m[8], l[8];
#pragma unroll
        for (int rr = 0; rr < 8; rr++) { m[rr] = -1e30f; l[rr] = 0.0f; }

        for (int kt = 0; kt <= qt; ++kt) {
            __syncthreads();  // prior tile compute done before overwriting sKt
            {
                const float* kbase = K + ((size_t)bh * S + kt * 128) * D;
                for (int i = tid; i < 128 * 16; i += 256) {
                    int col = i >> 4, c4 = i & 15;
                    float4 v = ((const float4*)(kbase + col * D))[c4];
                    sKt[(4 * c4 + 0) * PK + col] = v.x;
                    sKt[(4 * c4 + 1) * PK + col] = v.y;
                    sKt[(4 * c4 + 2) * PK + col] = v.z;
                    sKt[(4 * c4 + 3) * PK + col] = v.w;
                }
            }
            __syncthreads();

            unsigned long long acc[8][4];
#pragma unroll
            for (int rr = 0; rr < 8; rr++)
#pragma unroll
                for (int c = 0; c < 4; c++) acc[rr][c] = 0ull;

#pragma unroll 1
            for (int kk = 0; kk < 64; kk += 2) {
                float2 q2[8];
#pragma unroll
                for (int rr = 0; rr < 8; rr++)
                    q2[rr] = *((const float2*)(sQ + (ty + 16 * rr) * PQ + kk));
#pragma unroll
                for (int s = 0; s < 2; s++) {
                    unsigned long long kp[4];
#pragma unroll
                    for (int c = 0; c < 4; c++)
                        kp[c] = *((const unsigned long long*)(sKt + (kk + s) * PK + 2 * tx + 32 * c));
#pragma unroll
                    for (int rr = 0; rr < 8; rr++) {
                        unsigned long long qd = dup2(s ? q2[rr].y : q2[rr].x);
#pragma unroll
                        for (int c = 0; c < 4; c++) fma2(acc[rr][c], qd, kp[c]);
                    }
                }
            }

            const bool diag = (kt == qt);
#pragma unroll
            for (int rr = 0; rr < 8; rr++) {
                const int row = ty + 16 * rr;
                float sv[8];
                float tmax = -1e30f;
#pragma unroll
                for (int c = 0; c < 4; c++) {
                    float2 p = unpack2(acc[rr][c]);
                    const int col = 2 * tx + 32 * c;
                    float s0 = p.x * SCALE;
                    float s1 = p.y * SCALE;
                    if (diag) {
                        if (col > row) s0 = -1e9f;
                        if (col + 1 > row) s1 = -1e9f;
                    }
                    sv[2 * c] = s0;
                    sv[2 * c + 1] = s1;
                    tmax = fmaxf(tmax, fmaxf(s0, s1));
                }
                tmax = fmaxf(tmax, __shfl_xor_sync(0xffffffffu, tmax, 1));
                tmax = fmaxf(tmax, __shfl_xor_sync(0xffffffffu, tmax, 2));
                tmax = fmaxf(tmax, __shfl_xor_sync(0xffffffffu, tmax, 4));
                tmax = fmaxf(tmax, __shfl_xor_sync(0xffffffffu, tmax, 8));

                const float mn = fmaxf(m[rr], tmax);
                float psum = 0.0f;
#pragma unroll
                for (int cc = 0; cc < 8; cc++) psum += __expf(sv[cc] - mn);
                psum += __shfl_xor_sync(0xffffffffu, psum, 1);
                psum += __shfl_xor_sync(0xffffffffu, psum, 2);
                psum += __shfl_xor_sync(0xffffffffu, psum, 4);
                psum += __shfl_xor_sync(0xffffffffu, psum, 8);

                l[rr] = l[rr] * __expf(m[rr] - mn) + psum;
                m[rr] = mn;

                float* dst = SC + ((size_t)bh * S + r0 + row) * S + kt * 128;
#pragma unroll
                for (int c = 0; c < 4; c++)
                    *((float2*)(dst + 2 * tx + 32 * c)) = make_float2(sv[2 * c], sv[2 * c + 1]);
            }
        }

        if (tx == 0) {
#pragma unroll
            for (int rr = 0; rr < 8; rr++) {
                const int gi = bh * S + r0 + ty + 16 * rr;
                g_m[gi] = m[rr];
                g_l[gi] = l[rr];
            }
        }
    }
}

// ---------------------------------------------------------------------------
// Pass 2: probs = exp(s-m)/l -> gmem + smem; context = P @ V; zero-fill upper.
// Grid (8, 32), 128 threads. PV: thread owns 8 rows x 8 d (d packed f32x2).
// ---------------------------------------------------------------------------
__global__ void __launch_bounds__(128, 2)
attn_pass2(const float* __restrict__ V, float* __restrict__ SC,
           float* __restrict__ CTX)
{
    extern __shared__ float sm[];
    float* sV = sm;               // 128 x PV  (row-major V tile)
    float* sP = sm + 128 * PV;    // 128 x PP  (prob tile)

    const int tid = threadIdx.x;
    // prob-phase mapping: 16 col-lanes x 8 row-groups
    const int tx = tid & 15;
    const int ty = tid >> 4;      // 0..7 -> rows ty*16 + rr (rr<16)
    // PV mapping: 8 d-lanes x 16 row-groups
    const int dgrp = tid & 7;     // d = dgrp*8 + 2*dp + {0,1}
    const int rowgrp = tid >> 3;  // rows rowgrp*8 + rr2 (rr2<8)
    const int pid = blockIdx.x;
    const int bh = blockIdx.y;

    for (int half = 0; half < 2; ++half) {
        const int qt = half ? (15 - pid) : pid;
        const int r0 = qt * 128;

        float m[16], rl[16];
#pragma unroll
        for (int rr = 0; rr < 16; rr++) {
            const int gi = bh * S + r0 + ty * 16 + rr;
            m[rr] = g_m[gi];
            rl[rr] = 1.0f / g_l[gi];
        }

        unsigned long long acc[8][4];
#pragma unroll
        for (int rr = 0; rr < 8; rr++)
#pragma unroll
            for (int dp = 0; dp < 4; dp++) acc[rr][dp] = 0ull;

        for (int kt = 0; kt <= qt; ++kt) {
            __syncthreads();  // prior PV done before overwriting sV / sP
            {
                const float* vbase = V + ((size_t)bh * S + kt * 128) * D;
                for (int i = tid; i < 128 * 16; i += 128) {
                    int row = i >> 4, c4 = i & 15;
                    float4 v = ((const float4*)(vbase + row * D))[c4];
                    *((float4*)(sV + row * PV + 4 * c4)) = v;
                }
            }

            // probs: read raw scores, exponentiate, write gmem + smem
#pragma unroll 1
            for (int rr = 0; rr < 16; rr++) {
                const int row = ty * 16 + rr;
                float* srow = SC + ((size_t)bh * S + r0 + row) * S + kt * 128;
#pragma unroll
                for (int c = 0; c < 4; c++) {
                    const int col = 2 * tx + 32 * c;
                    float2 s2 = *((const float2*)(srow + col));
                    float p0 = __expf(s2.x - m[rr]) * rl[rr];
                    float p1 = __expf(s2.y - m[rr]) * rl[rr];
                    *((float2*)(srow + col)) = make_float2(p0, p1);
                    *((float2*)(sP + row * PP + col)) = make_float2(p0, p1);
                }
            }
            __syncthreads();

            // PV: ctx[row][d] += p[row][c] * v[c][d]
#pragma unroll 1
            for (int c = 0; c < 128; c += 2) {
                float2 p2[8];
#pragma unroll
                for (int rr = 0; rr < 8; rr++)
                    p2[rr] = *((const float2*)(sP + (rowgrp * 8 + rr) * PP + c));
#pragma unroll
                for (int s = 0; s < 2; s++) {
                    unsigned long long vv[4];
#pragma unroll
                    for (int dp = 0; dp < 4; dp++)
                        vv[dp] = *((const unsigned long long*)(sV + (c + s) * PV + dgrp * 8 + 2 * dp));
#pragma unroll
                    for (int rr = 0; rr < 8; rr++) {
                        unsigned long long pd = dup2(s ? p2[rr].y : p2[rr].x);
#pragma unroll
                        for (int dp = 0; dp < 4; dp++) fma2(acc[rr][dp], pd, vv[dp]);
                    }
                }
            }
        }

        // Zero-fill non-causal columns of this q-tile's prob rows
        {
            const int c0 = (qt + 1) * 128;
            if (c0 < S) {
                const int w4 = (S - c0) >> 2;
                const float4 z = make_float4(0.f, 0.f, 0.f, 0.f);
                for (int row = 0; row < 128; ++row) {
                    float4* base = (float4*)(SC + ((size_t)bh * S + r0 + row) * S + c0);
                    for (int i = tid; i < w4; i += 128) base[i] = z;
                }
            }
        }

        // Write context
#pragma unroll
        for (int rr = 0; rr < 8; rr++) {
            const int row = rowgrp * 8 + rr;
            float* crow = CTX + ((size_t)bh * S + r0 + row) * D + dgrp * 8;
#pragma unroll
            for (int dp = 0; dp < 4; dp++) {
                float2 o = unpack2(acc[rr][dp]);
                *((float2*)(crow + 2 * dp)) = o;
            }
        }
    }
}

// ---------------------------------------------------------------------------
extern "C" void kernel_launch(void* const* d_in, const int* in_sizes, int n_in,
                              void* d_out, int out_size)
{
    const float* q = (const float*)d_in[0];
    const float* k = (const float*)d_in[1];
    const float* v = (const float*)d_in[2];
    // d_in[3] = attn_mask (static causal) — unused

    float* out = (float*)d_out;
    float* ctx = out;                 // [BH, S, D]
    float* sc  = out + CTX_ELEMS;     // [BH, S, S] — scores scratch, then probs

    const int smem1 = (128 * PQ + 64 * PK) * sizeof(float);    // 69,120 B
    const int smem2 = (128 * PV + 128 * PP) * sizeof(float);   // 102,400 B
    cudaFuncSetAttribute(attn_pass1, cudaFuncAttributeMaxDynamicSharedMemorySize, smem1);
    cudaFuncSetAttribute(attn_pass2, cudaFuncAttributeMaxDynamicSharedMemorySize, smem2);

    dim3 grid(8, BH);   // paired q-tiles: uniform 17 k-tile units per CTA
    attn_pass1<<<grid, 256, smem1>>>(q, k, sc);
    attn_pass2<<<grid, 128, smem2>>>(v, sc, ctx);
}

// round 6
// speedup vs baseline: 1.3071x; 1.0491x over previous
#include <cuda_runtime.h>
#include <cstdint>

constexpr int S = 2048, D = 64;
constexpr int BH = 32;
constexpr float SCALE = 0.125f;
constexpr size_t CTX_ELEMS = (size_t)BH * S * D;

constexpr int PQ = 68;    // sQ pitch (mult of 4 -> float4 ok)
constexpr int PK = 134;   // sKt pitch (even -> 8B ok)
constexpr int PV = 68;    // sV pitch
constexpr int PP = 132;   // sP pitch (mult of 4)

__device__ float g_m[BH * S];
__device__ float g_l[BH * S];

// ---- packed fp32x2 helpers (FFMA2) ----
__device__ __forceinline__ unsigned long long pack2(float lo, float hi) {
    unsigned long long r;
    asm("mov.b64 %0, {%1, %2};" : "=l"(r) : "r"(__float_as_uint(lo)), "r"(__float_as_uint(hi)));
    return r;
}
__device__ __forceinline__ unsigned long long dup2(float x) { return pack2(x, x); }
__device__ __forceinline__ float2 unpack2(unsigned long long v) {
    unsigned int a, b;
    asm("mov.b64 {%0, %1}, %2;" : "=r"(a), "=r"(b) : "l"(v));
    return make_float2(__uint_as_float(a), __uint_as_float(b));
}
__device__ __forceinline__ void fma2(unsigned long long& d, unsigned long long a, unsigned long long b) {
    asm("fma.rn.f32x2 %0, %1, %2, %3;" : "=l"(d) : "l"(a), "l"(b), "l"(d));
}

// ---------------------------------------------------------------------------
// Pass 1: masked raw scores -> SC; online m/l -> g_m/g_l; zero-fill the
// non-causal region. Double-buffered K tile, one __syncthreads per tile.
// Grid (8, 32): CTA pid does q-tiles {pid, 15-pid}. 256 threads, 8x8/thread.
// ---------------------------------------------------------------------------
__global__ void __launch_bounds__(256, 2)
attn_pass1(const float* __restrict__ Q, const float* __restrict__ K,
           float* __restrict__ SC)
{
    extern __shared__ float sm[];
    float* sQ  = sm;                       // 128 x PQ
    float* sKt0 = sm + 128 * PQ;           // 64 x PK  (buffer 0)
    float* sKt1 = sKt0 + 64 * PK;          // 64 x PK  (buffer 1)

    const int tid = threadIdx.x;
    const int tx = tid & 15;
    const int ty = tid >> 4;
    const int pid = blockIdx.x;
    const int bh = blockIdx.y;

    // Zero-fill non-causal prob columns for both q-tiles (fire-and-forget STGs)
    {
        const float4 z = make_float4(0.f, 0.f, 0.f, 0.f);
#pragma unroll
        for (int half = 0; half < 2; ++half) {
            const int qt = half ? (15 - pid) : pid;
            const int c0 = (qt + 1) * 128;
            if (c0 < S) {
                const int w4 = (S - c0) >> 2;
                const int r0 = qt * 128;
                for (int i = tid; i < 128 * w4; i += 256) {
                    const int row = i / w4;
                    const int c4 = i - row * w4;
                    *((float4*)(SC + ((size_t)bh * S + r0 + row) * S + c0 + 4 * c4)) = z;
                }
            }
        }
    }

    for (int half = 0; half < 2; ++half) {
        const int qt = half ? (15 - pid) : pid;
        const int r0 = qt * 128;

        __syncthreads();  // stragglers of previous half done with sQ/sKt
        // Q tile + K tile 0 into buffer 0
        {
            const float* qbase = Q + ((size_t)bh * S + r0) * D;
            for (int i = tid; i < 128 * 16; i += 256) {
                int row = i >> 4, c4 = i & 15;
                float4 v = ((const float4*)(qbase + row * D))[c4];
                *((float4*)(sQ + row * PQ + c4 * 4)) = v;
            }
            const float* kbase = K + ((size_t)bh * S) * D;   // kt = 0
            for (int i = tid; i < 128 * 16; i += 256) {
                int col = i >> 4, c4 = i & 15;
                float4 v = ((const float4*)(kbase + col * D))[c4];
                sKt0[(4 * c4 + 0) * PK + col] = v.x;
                sKt0[(4 * c4 + 1) * PK + col] = v.y;
                sKt0[(4 * c4 + 2) * PK + col] = v.z;
                sKt0[(4 * c4 + 3) * PK + col] = v.w;
            }
        }

        float m[8], l[8];
#pragma unroll
        for (int rr = 0; rr < 8; rr++) { m[rr] = -1e30f; l[rr] = 0.0f; }

        for (int kt = 0; kt <= qt; ++kt) {
            __syncthreads();   // buf[kt&1] filled; all reads of it from kt-2 done
            const float* sKt = (kt & 1) ? sKt1 : sKt0;

            unsigned long long acc[8][4];
#pragma unroll
            for (int rr = 0; rr < 8; rr++)
#pragma unroll
                for (int c = 0; c < 4; c++) acc[rr][c] = 0ull;

#pragma unroll 1
            for (int kk = 0; kk < 64; kk += 2) {
                float2 q2[8];
#pragma unroll
                for (int rr = 0; rr < 8; rr++)
                    q2[rr] = *((const float2*)(sQ + (ty + 16 * rr) * PQ + kk));
#pragma unroll
                for (int s = 0; s < 2; s++) {
                    unsigned long long kp[4];
#pragma unroll
                    for (int c = 0; c < 4; c++)
                        kp[c] = *((const unsigned long long*)(sKt + (kk + s) * PK + 2 * tx + 32 * c));
#pragma unroll
                    for (int rr = 0; rr < 8; rr++) {
                        unsigned long long qd = dup2(s ? q2[rr].y : q2[rr].x);
#pragma unroll
                        for (int c = 0; c < 4; c++) fma2(acc[rr][c], qd, kp[c]);
                    }
                }
            }

            const bool diag = (kt == qt);
#pragma unroll
            for (int rr = 0; rr < 8; rr++) {
                const int row = ty + 16 * rr;
                float sv[8];
                float tmax = -1e30f;
#pragma unroll
                for (int c = 0; c < 4; c++) {
                    float2 p = unpack2(acc[rr][c]);
                    const int col = 2 * tx + 32 * c;
                    float s0 = p.x * SCALE;
                    float s1 = p.y * SCALE;
                    if (diag) {
                        if (col > row) s0 = -1e9f;
                        if (col + 1 > row) s1 = -1e9f;
                    }
                    sv[2 * c] = s0;
                    sv[2 * c + 1] = s1;
                    tmax = fmaxf(tmax, fmaxf(s0, s1));
                }
                tmax = fmaxf(tmax, __shfl_xor_sync(0xffffffffu, tmax, 1));
                tmax = fmaxf(tmax, __shfl_xor_sync(0xffffffffu, tmax, 2));
                tmax = fmaxf(tmax, __shfl_xor_sync(0xffffffffu, tmax, 4));
                tmax = fmaxf(tmax, __shfl_xor_sync(0xffffffffu, tmax, 8));

                const float mn = fmaxf(m[rr], tmax);
                float psum = 0.0f;
#pragma unroll
                for (int cc = 0; cc < 8; cc++) psum += __expf(sv[cc] - mn);
                psum += __shfl_xor_sync(0xffffffffu, psum, 1);
                psum += __shfl_xor_sync(0xffffffffu, psum, 2);
                psum += __shfl_xor_sync(0xffffffffu, psum, 4);
                psum += __shfl_xor_sync(0xffffffffu, psum, 8);

                l[rr] = l[rr] * __expf(m[rr] - mn) + psum;
                m[rr] = mn;

                float* dst = SC + ((size_t)bh * S + r0 + row) * S + kt * 128;
#pragma unroll
                for (int c = 0; c < 4; c++)
                    *((float2*)(dst + 2 * tx + 32 * c)) = make_float2(sv[2 * c], sv[2 * c + 1]);
            }

            // Prefetch next K tile into the other buffer (no extra sync needed:
            // everyone reading buf[(kt+1)&1] finished before this iter's top sync)
            if (kt < qt) {
                float* sKn = ((kt + 1) & 1) ? sKt1 : sKt0;
                const float* kbase = K + ((size_t)bh * S + (kt + 1) * 128) * D;
                for (int i = tid; i < 128 * 16; i += 256) {
                    int col = i >> 4, c4 = i & 15;
                    float4 v = ((const float4*)(kbase + col * D))[c4];
                    sKn[(4 * c4 + 0) * PK + col] = v.x;
                    sKn[(4 * c4 + 1) * PK + col] = v.y;
                    sKn[(4 * c4 + 2) * PK + col] = v.z;
                    sKn[(4 * c4 + 3) * PK + col] = v.w;
                }
            }
        }

        if (tx == 0) {
#pragma unroll
            for (int rr = 0; rr < 8; rr++) {
                const int gi = bh * S + r0 + ty + 16 * rr;
                g_m[gi] = m[rr];
                g_l[gi] = l[rr];
            }
        }
    }
}

// ---------------------------------------------------------------------------
// Pass 2: probs = exp(s-m)/l -> gmem + smem; context = P @ V.
// Grid (8, 32), 256 threads. Prob phase: 8 rows x 8 cols (float4 IO).
// PV phase: 4 rows x 8 d per thread (f32x2 pairs).
// ---------------------------------------------------------------------------
__global__ void __launch_bounds__(256, 2)
attn_pass2(const float* __restrict__ V, float* __restrict__ SC,
           float* __restrict__ CTX)
{
    extern __shared__ float sm[];
    float* sV = sm;               // 128 x PV
    float* sP = sm + 128 * PV;    // 128 x PP

    const int tid = threadIdx.x;
    // prob phase: 16 col-lanes x 16 row-groups (8 rows each)
    const int tx = tid & 15;
    const int ty = tid >> 4;
    // PV phase: 8 d-lanes (8 d each) x 32 row-groups (4 rows each)
    const int dgrp = tid & 7;
    const int rowgrp = tid >> 3;
    const int pid = blockIdx.x;
    const int bh = blockIdx.y;

    for (int half = 0; half < 2; ++half) {
        const int qt = half ? (15 - pid) : pid;
        const int r0 = qt * 128;

        float m[8], rl[8];
#pragma unroll
        for (int rr = 0; rr < 8; rr++) {
            const int gi = bh * S + r0 + ty * 8 + rr;
            m[rr] = g_m[gi];
            rl[rr] = 1.0f / g_l[gi];
        }

        unsigned long long acc[4][4];
#pragma unroll
        for (int rr = 0; rr < 4; rr++)
#pragma unroll
            for (int dp = 0; dp < 4; dp++) acc[rr][dp] = 0ull;

        for (int kt = 0; kt <= qt; ++kt) {
            __syncthreads();  // prior PV done before overwriting sV / sP
            {
                const float* vbase = V + ((size_t)bh * S + kt * 128) * D;
                for (int i = tid; i < 128 * 16; i += 256) {
                    int row = i >> 4, c4 = i & 15;
                    float4 v = ((const float4*)(vbase + row * D))[c4];
                    *((float4*)(sV + row * PV + 4 * c4)) = v;
                }
            }

            // probs: float4 read scores, exp, float4 write gmem + smem
#pragma unroll 1
            for (int rr = 0; rr < 8; rr++) {
                const int row = ty * 8 + rr;
                float* srow = SC + ((size_t)bh * S + r0 + row) * S + kt * 128;
#pragma unroll
                for (int cc = 0; cc < 2; cc++) {
                    const int col = 4 * tx + 64 * cc;
                    float4 s4 = *((const float4*)(srow + col));
                    float4 p4;
                    p4.x = __expf(s4.x - m[rr]) * rl[rr];
                    p4.y = __expf(s4.y - m[rr]) * rl[rr];
                    p4.z = __expf(s4.z - m[rr]) * rl[rr];
                    p4.w = __expf(s4.w - m[rr]) * rl[rr];
                    *((float4*)(srow + col)) = p4;
                    *((float4*)(sP + row * PP + col)) = p4;
                }
            }
            __syncthreads();

            // PV: ctx[row][d] += p[row][c] * v[c][d]
#pragma unroll 1
            for (int c = 0; c < 128; c += 2) {
                float2 p2[4];
#pragma unroll
                for (int rr = 0; rr < 4; rr++)
                    p2[rr] = *((const float2*)(sP + (rowgrp * 4 + rr) * PP + c));
#pragma unroll
                for (int s = 0; s < 2; s++) {
                    unsigned long long vv[4];
#pragma unroll
                    for (int dp = 0; dp < 4; dp++)
                        vv[dp] = *((const unsigned long long*)(sV + (c + s) * PV + dgrp * 8 + 2 * dp));
#pragma unroll
                    for (int rr = 0; rr < 4; rr++) {
                        unsigned long long pd = dup2(s ? p2[rr].y : p2[rr].x);
#pragma unroll
                        for (int dp = 0; dp < 4; dp++) fma2(acc[rr][dp], pd, vv[dp]);
                    }
                }
            }
        }

        // Write context: rows rowgrp*4+rr, cols dgrp*8 .. +8
#pragma unroll
        for (int rr = 0; rr < 4; rr++) {
            const int row = rowgrp * 4 + rr;
            float* crow = CTX + ((size_t)bh * S + r0 + row) * D + dgrp * 8;
#pragma unroll
            for (int dp = 0; dp < 4; dp++) {
                float2 o = unpack2(acc[rr][dp]);
                *((float2*)(crow + 2 * dp)) = o;
            }
        }
    }
}

// ---------------------------------------------------------------------------
extern "C" void kernel_launch(void* const* d_in, const int* in_sizes, int n_in,
                              void* d_out, int out_size)
{
    const float* q = (const float*)d_in[0];
    const float* k = (const float*)d_in[1];
    const float* v = (const float*)d_in[2];

    float* out = (float*)d_out;
    float* ctx = out;                 // [BH, S, D]
    float* sc  = out + CTX_ELEMS;     // [BH, S, S]

    const int smem1 = (128 * PQ + 2 * 64 * PK) * sizeof(float);  // 103,424 B
    const int smem2 = (128 * PV + 128 * PP) * sizeof(float);     // 102,400 B
    cudaFuncSetAttribute(attn_pass1, cudaFuncAttributeMaxDynamicSharedMemorySize, smem1);
    cudaFuncSetAttribute(attn_pass2, cudaFuncAttributeMaxDynamicSharedMemorySize, smem2);

    dim3 grid(8, BH);
    attn_pass1<<<grid, 256, smem1>>>(q, k, sc);
    attn_pass2<<<grid, 256, smem2>>>(v, sc, ctx);
}